// round 9
// baseline (speedup 1.0000x reference)
#include <cuda_runtime.h>
#include <cuda_bf16.h>
#include <cstdint>

// MatrixExpander: out(16,16,512,512) = kron(A(16,16,64,64), ones(8,8)), fp32.
//
// Established R1-R8: job is pinned at the path-independent SM->LTS write cap
// (~6300 B/cyc -> 6.58 TB/s measured, kernel floor ~40.5us). R9 keeps the
// winning 2KB-row smem->TMA-bulk design (R8) and removes the last non-floor
// costs: CTA churn and end-of-CTA drains.
//
//   - persistent: 2048 CTAs x 8 tiles each (grid-stride)
//   - two 2 KB row buffers per CTA, conflict-free fill (thread t -> slot t)
//   - one commit group (8 x 2 KB bulk stores) per tile; backpressure via
//     wait_group.read 1 so ~2 groups stay in flight per CTA at all times
//   - single full drain before exit

__device__ __forceinline__ uint32_t smem_u32(const void* p) {
    uint32_t a;
    asm("{ .reg .u64 t; cvta.to.shared.u64 t, %1; cvt.u32.u64 %0, t; }"
        : "=r"(a) : "l"(p));
    return a;
}

static constexpr uint32_t NTILES = 16384;   // 16*16*64, 4096 floats each
static constexpr uint32_t NCTAS  = 2048;    // 8 tiles per CTA

__global__ __launch_bounds__(128)
void expander_tma_r9_kernel(const float* __restrict__ A, float* __restrict__ out)
{
    __shared__ __align__(128) float4 row[2][128];   // 2 x 2 KB expanded rows

    const uint32_t t = threadIdx.x;   // [0, 128)

    uint32_t it = 0;
    for (uint32_t c = blockIdx.x; c < NTILES; c += NCTAS, ++it) {
        // Load this tile's A value early (slot t -> output cols [4t,4t+4)
        // -> A col t>>1; adjacent threads broadcast from the same address).
        const float v = __ldg(A + (c << 6) + (t >> 1));

        // Backpressure: before overwriting buffer (it & 1), ensure all groups
        // except possibly the previous one have been fully READ out of smem.
        if (it >= 2) {
            if (t == 0)
                asm volatile("cp.async.bulk.wait_group.read 1;" ::: "memory");
            __syncthreads();
        }

        row[it & 1u][t] = make_float4(v, v, v, v);
        __syncthreads();

        if (t == 0) {
            // Order generic-proxy STS before async-proxy bulk reads.
            asm volatile("fence.proxy.async.shared::cta;" ::: "memory");
            const uint32_t s = smem_u32(row[it & 1u]);
            float* dst = out + ((size_t)c << 12);   // c * 4096 floats
            #pragma unroll
            for (int r = 0; r < 8; ++r) {
                asm volatile(
                    "cp.async.bulk.global.shared::cta.bulk_group [%0], [%1], %2;"
                    :: "l"(dst + (r << 9)), "r"(s), "n"(2048) : "memory");
            }
            asm volatile("cp.async.bulk.commit_group;" ::: "memory");
        }
    }

    // Drain all groups before CTA exit (smem may be reallocated).
    if (t == 0)
        asm volatile("cp.async.bulk.wait_group 0;" ::: "memory");
}

extern "C" void kernel_launch(void* const* d_in, const int* in_sizes, int n_in,
                              void* d_out, int out_size)
{
    const float* A = (const float*)d_in[0];   // (16,16,64,64) fp32
    float* out = (float*)d_out;               // (16,16,512,512) fp32

    expander_tma_r9_kernel<<<NCTAS, 128>>>(A, out);
}

// round 10
// speedup vs baseline: 1.1174x; 1.1174x over previous
#include <cuda_runtime.h>
#include <cuda_bf16.h>
#include <cstdint>

// MatrixExpander: out(16,16,512,512) = kron(A(16,16,64,64), ones(8,8)), fp32.
//
// Pinned at the path-independent SM->LTS write cap (~6.58 TB/s measured on
// R7/R8; all 268 MB must cross LTS once -> ~40.7us kernel floor). R10 merges
// the two floor-sitting designs to shave command/CTA overhead:
//   - one-shot CTAs (R9 proved persistent loops REDUCE store parallelism)
//   - 8192 CTAs x 128 threads, TWO tiles per CTA
//   - per tile: build the 2 KB expanded row once in smem (conflict-free,
//     thread t -> slot t) and emit 8 x 2 KB bulk stores from it (R8 reuse)
//   - 4 KB smem/CTA -> high occupancy; single commit group + one drain

__device__ __forceinline__ uint32_t smem_u32(const void* p) {
    uint32_t a;
    asm("{ .reg .u64 t; cvta.to.shared.u64 t, %1; cvt.u32.u64 %0, t; }"
        : "=r"(a) : "l"(p));
    return a;
}

__global__ __launch_bounds__(128)
void expander_tma_r10_kernel(const float* __restrict__ A, float* __restrict__ out)
{
    __shared__ __align__(128) float4 row[2][128];   // two 2 KB expanded rows

    const uint32_t cta = blockIdx.x;    // [0, 8192)
    const uint32_t t   = threadIdx.x;   // [0, 128)
    const uint32_t c0  = cta << 1;      // first of two adjacent tiles

    // Slot t covers output cols [4t,4t+4) -> A col t>>1 (adjacent threads
    // broadcast). Two scalar loads, 64 floats apart.
    const uint32_t colofs = t >> 1;
    const float v0 = __ldg(A + (c0 << 6)        + colofs);
    const float v1 = __ldg(A + ((c0 | 1u) << 6) + colofs);
    row[0][t] = make_float4(v0, v0, v0, v0);
    row[1][t] = make_float4(v1, v1, v1, v1);

    __syncthreads();

    if (t == 0) {
        // Order generic-proxy STS before async-proxy bulk reads.
        asm volatile("fence.proxy.async.shared::cta;" ::: "memory");
        const uint32_t s0 = smem_u32(row[0]);
        const uint32_t s1 = smem_u32(row[1]);
        float* dst = out + ((size_t)c0 << 12);   // 2 tiles = 8192 floats
        #pragma unroll
        for (int r = 0; r < 8; ++r) {
            asm volatile(
                "cp.async.bulk.global.shared::cta.bulk_group [%0], [%1], %2;"
                :: "l"(dst + (r << 9)), "r"(s0), "n"(2048) : "memory");
        }
        #pragma unroll
        for (int r = 8; r < 16; ++r) {
            asm volatile(
                "cp.async.bulk.global.shared::cta.bulk_group [%0], [%1], %2;"
                :: "l"(dst + (r << 9)), "r"(s1), "n"(2048) : "memory");
        }
        asm volatile("cp.async.bulk.commit_group;" ::: "memory");
        asm volatile("cp.async.bulk.wait_group 0;" ::: "memory");
    }
}

extern "C" void kernel_launch(void* const* d_in, const int* in_sizes, int n_in,
                              void* d_out, int out_size)
{
    const float* A = (const float*)d_in[0];   // (16,16,64,64) fp32
    float* out = (float*)d_out;               // (16,16,512,512) fp32

    // 8192 CTAs x 2 tiles x 16 KB... (each tile = 8 x 2 KB stores) = 256 MiB
    expander_tma_r10_kernel<<<8192, 128>>>(A, out);
}

// round 11
// speedup vs baseline: 1.1766x; 1.0530x over previous
#include <cuda_runtime.h>
#include <cuda_bf16.h>
#include <cstdint>

// MatrixExpander: out(16,16,512,512) = kron(A(16,16,64,64), ones(8,8)), fp32.
//
// FINAL (= R7, best bench 43.5us / kernel 40.8us = 6.57 TB/s effective write,
// pinned at the path-independent SM->LTS write-ingress cap of ~6300 B/cyc).
//
// Design: one CTA per tile. Tile c in [0,16384) covers out[c*4096 .. +4096)
// (16 KB contiguous) = 8 copies of the 512-float expanded row of A-row c,
// expanded[j] = A[c*64 + j/8]. Build the 16 KB tile in smem with a
// CONFLICT-FREE fill, push with ONE cp.async.bulk store.
//
// Verified-dead alternatives (R1-R10): plain STG (5.0 TB/s), STG/TMA hybrids
// (<=6.2), persistent CTAs (-10%), 2-tile CTAs (-1.5%), 8x smem reuse
// (equal kernel, worse bench), conflicted fill (-45%).
//
// Fill layout: thread t writes float4 slots {t, t+256, t+512, t+768}:
//   - 16 B lane stride -> fully coalesced, zero bank conflicts
//   - all four slots need the SAME A col (t & 127) >> 1 -> one scalar load
//     (adjacent-thread broadcast), one splat, 4 STS.128.

__device__ __forceinline__ uint32_t smem_u32(const void* p) {
    uint32_t a;
    asm("{ .reg .u64 t; cvta.to.shared.u64 t, %1; cvt.u32.u64 %0, t; }"
        : "=r"(a) : "l"(p));
    return a;
}

__global__ __launch_bounds__(256)
void expander_tma_kernel(const float* __restrict__ A, float* __restrict__ out)
{
    __shared__ __align__(128) float4 buf[1024];   // 16 KB = 8 output rows

    const uint32_t c = blockIdx.x;   // tile id in [0, 16384)
    const uint32_t t = threadIdx.x;  // [0, 256)

    // One A value per thread (pairs of adjacent threads share -> broadcast).
    const float v = __ldg(A + (c << 6) + ((t & 127u) >> 1));
    const float4 v4 = make_float4(v, v, v, v);

    buf[t        ] = v4;
    buf[t + 256u ] = v4;
    buf[t + 512u ] = v4;
    buf[t + 768u ] = v4;

    __syncthreads();

    if (t == 0) {
        // Order generic-proxy STS before async-proxy bulk read.
        asm volatile("fence.proxy.async.shared::cta;" ::: "memory");
        const uint32_t s = smem_u32(buf);
        const float* dst = out + ((size_t)c << 12);   // c * 16 KB
        asm volatile(
            "cp.async.bulk.global.shared::cta.bulk_group [%0], [%1], %2;"
            :: "l"(dst), "r"(s), "n"(16384) : "memory");
        asm volatile("cp.async.bulk.commit_group;" ::: "memory");
        asm volatile("cp.async.bulk.wait_group 0;" ::: "memory");
    }
}

extern "C" void kernel_launch(void* const* d_in, const int* in_sizes, int n_in,
                              void* d_out, int out_size)
{
    const float* A = (const float*)d_in[0];   // (16,16,64,64) fp32
    float* out = (float*)d_out;               // (16,16,512,512) fp32

    // 16384 tiles x 16 KB = 256 MiB output
    expander_tma_kernel<<<16384, 256>>>(A, out);
}